// round 2
// baseline (speedup 1.0000x reference)
#include <cuda_runtime.h>
#include <cstdint>

#define BATCH   4
#define HEADS   16
#define SEQ     2048
#define DMODEL  1024
#define HDIM    64
#define TOK     (BATCH*SEQ)       // 8192
#define SCALE   0.125f            // 1/sqrt(64)

// -------- scratch (allocation-free rule: __device__ globals) --------
__device__ float g_Q[BATCH*HEADS*SEQ*HDIM];   // [b][h][l][dh]
__device__ float g_K[BATCH*HEADS*SEQ*HDIM];
__device__ float g_V[BATCH*HEADS*SEQ*HDIM];
__device__ float g_O[TOK*DMODEL];             // [b*l][h*64+dh]

__device__ __forceinline__ float to_tf32(float x) {
    float r;
    asm("cvt.rna.tf32.f32 %0, %1;" : "=f"(r) : "f"(x));
    return r;
}

__device__ __forceinline__ void mma_tf32(float c[4],
    uint32_t a0, uint32_t a1, uint32_t a2, uint32_t a3,
    uint32_t b0, uint32_t b1)
{
    asm volatile(
        "mma.sync.aligned.m16n8k8.row.col.f32.tf32.tf32.f32 "
        "{%0,%1,%2,%3}, {%4,%5,%6,%7}, {%8,%9}, {%0,%1,%2,%3};\n"
        : "+f"(c[0]), "+f"(c[1]), "+f"(c[2]), "+f"(c[3])
        : "r"(a0), "r"(a1), "r"(a2), "r"(a3), "r"(b0), "r"(b1));
}

__device__ __forceinline__ float neg_inf() { return __int_as_float(0xff800000); }

// ============================================================================
// Generic TF32 tensor-core GEMM tile kernel.
//  EPI 0: out[row*DMODEL+col] = acc + bias[col]                  (final proj)
//  EPI 1: QKV scatter: out[((b*H+h)*SEQ+l)*HDIM+dh] = acc+bias   (projections)
//  EPI 2: scores: v=acc*SCALE; mask -> -inf; attn[(h*B+b)][row][col]=v
//  EPI 3: PV: g_O[(b*SEQ+row)*DMODEL + h*64 + col] = acc
//  BT=false: B element (k,n) at B[k*ldb + n]   (row-major KxN)
//  BT=true : B element (k,n) at B[n*ldb + k]   (K stored [n][k], used for Q.K^T)
// ============================================================================
template<int BM, int BN, int BK, int WM, int WN, bool BT, int EPI>
__global__ void __launch_bounds__(256)
gemm_mma(const float* __restrict__ Ag, const float* __restrict__ Bg,
         const float* __restrict__ bias, const int* __restrict__ mask,
         float* __restrict__ out, int K, int lda, int ldb)
{
    constexpr int WARPS_M = BM / WM;
    constexpr int MT = WM / 16;
    constexpr int NT = WN / 8;
    constexpr int PAD = 4;

    __shared__ float As[BM][BK + PAD];
    __shared__ float Bs[BK][BN + PAD];

    const int tid  = threadIdx.x;
    const int warp = tid >> 5;
    const int lane = tid & 31;
    const int wm   = warp % WARPS_M;
    const int wn   = warp / WARPS_M;
    const int g    = lane >> 2;   // groupID
    const int t4   = lane & 3;    // threadID in group

    const int bn = blockIdx.x * BN;
    const int bm = blockIdx.y * BM;
    const int z  = blockIdx.z;

    const float* A = Ag;
    const float* B = Bg;
    int zb = 0, zh = 0;
    if (EPI == 2) {
        zb = z / HEADS; zh = z % HEADS;
        A += (size_t)z * SEQ * HDIM;
        B += (size_t)z * SEQ * HDIM;
    }
    if (EPI == 3) {
        zb = z / HEADS; zh = z % HEADS;
        A += ((size_t)(zh * BATCH + zb)) * SEQ * SEQ;   // attn [h][b][l][t]
        B += (size_t)z * SEQ * HDIM;                    // V [b][h][t][dv]
    }

    float acc[MT][NT][4];
    #pragma unroll
    for (int mi = 0; mi < MT; ++mi)
        #pragma unroll
        for (int ni = 0; ni < NT; ++ni)
            #pragma unroll
            for (int e = 0; e < 4; ++e) acc[mi][ni][e] = 0.f;

    for (int k0 = 0; k0 < K; k0 += BK) {
        // ---- stage A tile: BM x BK (row-major), float4 + tf32 convert ----
        constexpr int AV = BM * BK / 4;
        #pragma unroll
        for (int i = 0; i < AV / 256; ++i) {
            int v = i * 256 + tid;
            int row = v / (BK / 4);
            int kc  = (v % (BK / 4)) * 4;
            float4 x = *(const float4*)(A + (size_t)(bm + row) * lda + k0 + kc);
            x.x = to_tf32(x.x); x.y = to_tf32(x.y);
            x.z = to_tf32(x.z); x.w = to_tf32(x.w);
            *(float4*)(&As[row][kc]) = x;
        }
        // ---- stage B tile: BK x BN ----
        if (!BT) {
            constexpr int BV = BK * BN / 4;
            #pragma unroll
            for (int i = 0; i < BV / 256; ++i) {
                int v = i * 256 + tid;
                int row = v / (BN / 4);
                int col = (v % (BN / 4)) * 4;
                float4 x = *(const float4*)(B + (size_t)(k0 + row) * ldb + bn + col);
                x.x = to_tf32(x.x); x.y = to_tf32(x.y);
                x.z = to_tf32(x.z); x.w = to_tf32(x.w);
                *(float4*)(&Bs[row][col]) = x;
            }
        } else {
            constexpr int BE = BK * BN;
            #pragma unroll
            for (int i = 0; i < BE / 256; ++i) {
                int v = i * 256 + tid;
                int kk  = v % BK;
                int col = v / BK;
                float x = B[(size_t)(bn + col) * ldb + k0 + kk];
                Bs[kk][col] = to_tf32(x);
            }
        }
        __syncthreads();

        // ---- compute: k-steps of 8 ----
        #pragma unroll
        for (int kk = 0; kk < BK; kk += 8) {
            uint32_t af[MT][4];
            uint32_t bf[NT][2];
            #pragma unroll
            for (int mi = 0; mi < MT; ++mi) {
                int r = wm * WM + mi * 16;
                af[mi][0] = __float_as_uint(As[r + g    ][kk + t4    ]);
                af[mi][1] = __float_as_uint(As[r + g + 8][kk + t4    ]);
                af[mi][2] = __float_as_uint(As[r + g    ][kk + t4 + 4]);
                af[mi][3] = __float_as_uint(As[r + g + 8][kk + t4 + 4]);
            }
            #pragma unroll
            for (int ni = 0; ni < NT; ++ni) {
                int c = wn * WN + ni * 8 + g;
                bf[ni][0] = __float_as_uint(Bs[kk + t4    ][c]);
                bf[ni][1] = __float_as_uint(Bs[kk + t4 + 4][c]);
            }
            #pragma unroll
            for (int mi = 0; mi < MT; ++mi)
                #pragma unroll
                for (int ni = 0; ni < NT; ++ni)
                    mma_tf32(acc[mi][ni], af[mi][0], af[mi][1], af[mi][2], af[mi][3],
                             bf[ni][0], bf[ni][1]);
        }
        __syncthreads();
    }

    // ---- epilogue ----
    #pragma unroll
    for (int mi = 0; mi < MT; ++mi) {
        #pragma unroll
        for (int ni = 0; ni < NT; ++ni) {
            #pragma unroll
            for (int e = 0; e < 4; ++e) {
                int row = bm + wm * WM + mi * 16 + g + ((e >= 2) ? 8 : 0);
                int col = bn + wn * WN + ni * 8 + t4 * 2 + (e & 1);
                float v = acc[mi][ni][e];
                if (EPI == 0) {
                    v += bias[col];
                    out[(size_t)row * DMODEL + col] = v;
                } else if (EPI == 1) {
                    v += bias[col];
                    int b  = row >> 11;          // row / SEQ
                    int l  = row & (SEQ - 1);
                    int h  = col >> 6;           // col / HDIM
                    int dh = col & (HDIM - 1);
                    out[(((size_t)(b * HEADS + h)) * SEQ + l) * HDIM + dh] = v;
                } else if (EPI == 2) {
                    v *= SCALE;
                    if (mask[zb * SEQ + col] != 0) v = neg_inf();
                    out[(((size_t)(zh * BATCH + zb)) * SEQ + row) * SEQ + col] = v;
                } else { // EPI == 3
                    out[((size_t)(zb * SEQ + row)) * DMODEL + zh * HDIM + col] = v;
                }
            }
        }
    }
}

// ============================================================================
// Row softmax over attn buffer: one block (256 threads) per row of 2048.
// Handles fully-masked rows (max == -inf) -> all zeros (matches nan_to_num).
// ============================================================================
__global__ void __launch_bounds__(256) softmax_kernel(float* __restrict__ attn)
{
    __shared__ float red[8];
    __shared__ float bcast;
    const size_t row = blockIdx.x;
    float* p = attn + row * SEQ;
    const int tid = threadIdx.x;

    float4 x0 = ((const float4*)p)[tid];
    float4 x1 = ((const float4*)p)[tid + 256];

    float m = fmaxf(fmaxf(fmaxf(x0.x, x0.y), fmaxf(x0.z, x0.w)),
                    fmaxf(fmaxf(x1.x, x1.y), fmaxf(x1.z, x1.w)));
    #pragma unroll
    for (int o = 16; o; o >>= 1) m = fmaxf(m, __shfl_xor_sync(0xffffffffu, m, o));
    if ((tid & 31) == 0) red[tid >> 5] = m;
    __syncthreads();
    if (tid < 32) {
        float t = (tid < 8) ? red[tid] : __int_as_float(0xff800000);
        #pragma unroll
        for (int o = 4; o; o >>= 1) t = fmaxf(t, __shfl_xor_sync(0xffffffffu, t, o));
        if (tid == 0) bcast = t;
    }
    __syncthreads();
    m = bcast;

    if (isinf(m) && m < 0.f) {   // fully masked row -> zeros
        float4 zz = make_float4(0.f, 0.f, 0.f, 0.f);
        ((float4*)p)[tid] = zz;
        ((float4*)p)[tid + 256] = zz;
        return;
    }

    float4 e0, e1;
    e0.x = __expf(x0.x - m); e0.y = __expf(x0.y - m);
    e0.z = __expf(x0.z - m); e0.w = __expf(x0.w - m);
    e1.x = __expf(x1.x - m); e1.y = __expf(x1.y - m);
    e1.z = __expf(x1.z - m); e1.w = __expf(x1.w - m);

    float s = (e0.x + e0.y) + (e0.z + e0.w) + (e1.x + e1.y) + (e1.z + e1.w);
    #pragma unroll
    for (int o = 16; o; o >>= 1) s += __shfl_xor_sync(0xffffffffu, s, o);
    __syncthreads();   // everyone has read bcast(m); safe to reuse shared
    if ((tid & 31) == 0) red[tid >> 5] = s;
    __syncthreads();
    if (tid < 32) {
        float t = (tid < 8) ? red[tid] : 0.f;
        #pragma unroll
        for (int o = 4; o; o >>= 1) t += __shfl_xor_sync(0xffffffffu, t, o);
        if (tid == 0) bcast = t;
    }
    __syncthreads();
    const float inv = 1.0f / bcast;

    e0.x *= inv; e0.y *= inv; e0.z *= inv; e0.w *= inv;
    e1.x *= inv; e1.y *= inv; e1.z *= inv; e1.w *= inv;
    ((float4*)p)[tid] = e0;
    ((float4*)p)[tid + 256] = e1;
}

// ============================================================================
extern "C" void kernel_launch(void* const* d_in, const int* in_sizes, int n_in,
                              void* d_out, int out_size)
{
    const float* q    = (const float*)d_in[0];
    const float* k    = (const float*)d_in[1];
    const float* v    = (const float*)d_in[2];
    const int*   mask = (const int*)d_in[3];
    const float* Wq = (const float*)d_in[4];
    const float* bq = (const float*)d_in[5];
    const float* Wk = (const float*)d_in[6];
    const float* bk = (const float*)d_in[7];
    const float* Wv = (const float*)d_in[8];
    const float* bv = (const float*)d_in[9];
    const float* Wo = (const float*)d_in[10];
    const float* bo = (const float*)d_in[11];

    float* out  = (float*)d_out;                         // [4,2048,1024]
    float* attn = out + (size_t)TOK * DMODEL;            // [16,4,2048,2048]

    float *gq, *gk, *gv, *go;
    cudaGetSymbolAddress((void**)&gq, g_Q);
    cudaGetSymbolAddress((void**)&gk, g_K);
    cudaGetSymbolAddress((void**)&gv, g_V);
    cudaGetSymbolAddress((void**)&go, g_O);

    dim3 blk(256);

    // Q/K/V projections: [8192,1024] @ [1024,1024] + b, scatter to heads
    dim3 gproj(DMODEL / 128, TOK / 128, 1);
    gemm_mma<128,128,32,32,64,false,1><<<gproj, blk>>>(q, Wq, bq, nullptr, gq, DMODEL, DMODEL, DMODEL);
    gemm_mma<128,128,32,32,64,false,1><<<gproj, blk>>>(k, Wk, bk, nullptr, gk, DMODEL, DMODEL, DMODEL);
    gemm_mma<128,128,32,32,64,false,1><<<gproj, blk>>>(v, Wv, bv, nullptr, gv, DMODEL, DMODEL, DMODEL);

    // scores: per (b,h)  S = scale * Q K^T  (+ mask), written raw to attn buf
    dim3 gsc(SEQ / 128, SEQ / 128, BATCH * HEADS);
    gemm_mma<128,128,32,32,64,true,2><<<gsc, blk>>>(gq, gk, nullptr, mask, attn, HDIM, HDIM, HDIM);

    // row softmax in place over attn
    softmax_kernel<<<BATCH * HEADS * SEQ, blk>>>(attn);

    // PV: per (b,h)  O = P @ V  -> g_O [b*l][h*64+dv]
    dim3 gpv(1, SEQ / 128, BATCH * HEADS);
    gemm_mma<128,64,32,32,32,false,3><<<gpv, blk>>>(attn, gv, nullptr, nullptr, go, SEQ, SEQ, HDIM);

    // output projection: [8192,1024] @ Wo + bo -> out
    gemm_mma<128,128,32,32,64,false,0><<<gproj, blk>>>(go, Wo, bo, nullptr, out, DMODEL, DMODEL, DMODEL);
}

// round 3
// speedup vs baseline: 1.2606x; 1.2606x over previous
#include <cuda_runtime.h>
#include <cstdint>

#define BATCH   4
#define HEADS   16
#define SEQ     2048
#define DMODEL  1024
#define HDIM    64
#define TOK     (BATCH*SEQ)       // 8192
// softmax in exp2 domain: scale = (1/sqrt(64)) * log2(e)
#define SCALE2  0.18033688011112042f

#define QB      128               // query rows per fused block
#define TC      128               // key-column tile

// -------- scratch (allocation-free rule: __device__ globals) --------
__device__ float g_Q[BATCH*HEADS*SEQ*HDIM];   // [b][h][l][dh]
__device__ float g_K[BATCH*HEADS*SEQ*HDIM];
__device__ float g_V[BATCH*HEADS*SEQ*HDIM];
__device__ float g_O[TOK*DMODEL];             // [b*l][h*64+dh]

__device__ __forceinline__ float to_tf32(float x) {
    float r;
    asm("cvt.rna.tf32.f32 %0, %1;" : "=f"(r) : "f"(x));
    return r;
}

__device__ __forceinline__ float ex2(float x) {
    float r;
    asm("ex2.approx.f32 %0, %1;" : "=f"(r) : "f"(x));
    return r;
}

__device__ __forceinline__ void mma_tf32(float c[4],
    uint32_t a0, uint32_t a1, uint32_t a2, uint32_t a3,
    uint32_t b0, uint32_t b1)
{
    asm volatile(
        "mma.sync.aligned.m16n8k8.row.col.f32.tf32.tf32.f32 "
        "{%0,%1,%2,%3}, {%4,%5,%6,%7}, {%8,%9}, {%0,%1,%2,%3};\n"
        : "+f"(c[0]), "+f"(c[1]), "+f"(c[2]), "+f"(c[3])
        : "r"(a0), "r"(a1), "r"(a2), "r"(a3), "r"(b0), "r"(b1));
}

#define NEG_INF __int_as_float(0xff800000)

// ============================================================================
// Projection / output GEMM (TF32 mma). EPI 0: +bias, row-major out.
// EPI 1: +bias, scatter to [b][h][l][dh].
// ============================================================================
template<int BM, int BN, int BK, int WM, int WN, int EPI>
__global__ void __launch_bounds__(256)
gemm_mma(const float* __restrict__ Ag, const float* __restrict__ Bg,
         const float* __restrict__ bias, float* __restrict__ out,
         int K, int lda, int ldb)
{
    constexpr int WARPS_M = BM / WM;
    constexpr int MT = WM / 16;
    constexpr int NT = WN / 8;
    constexpr int PAD = 4;

    __shared__ float As[BM][BK + PAD];
    __shared__ float Bs[BK][BN + PAD];

    const int tid  = threadIdx.x;
    const int warp = tid >> 5;
    const int lane = tid & 31;
    const int wm   = warp % WARPS_M;
    const int wn   = warp / WARPS_M;
    const int g    = lane >> 2;
    const int t4   = lane & 3;

    const int bn = blockIdx.x * BN;
    const int bm = blockIdx.y * BM;

    float acc[MT][NT][4];
    #pragma unroll
    for (int mi = 0; mi < MT; ++mi)
        #pragma unroll
        for (int ni = 0; ni < NT; ++ni)
            #pragma unroll
            for (int e = 0; e < 4; ++e) acc[mi][ni][e] = 0.f;

    for (int k0 = 0; k0 < K; k0 += BK) {
        constexpr int AV = BM * BK / 4;
        #pragma unroll
        for (int i = 0; i < AV / 256; ++i) {
            int v = i * 256 + tid;
            int row = v / (BK / 4);
            int kc  = (v % (BK / 4)) * 4;
            float4 x = *(const float4*)(Ag + (size_t)(bm + row) * lda + k0 + kc);
            x.x = to_tf32(x.x); x.y = to_tf32(x.y);
            x.z = to_tf32(x.z); x.w = to_tf32(x.w);
            *(float4*)(&As[row][kc]) = x;
        }
        constexpr int BV = BK * BN / 4;
        #pragma unroll
        for (int i = 0; i < BV / 256; ++i) {
            int v = i * 256 + tid;
            int row = v / (BN / 4);
            int col = (v % (BN / 4)) * 4;
            float4 x = *(const float4*)(Bg + (size_t)(k0 + row) * ldb + bn + col);
            x.x = to_tf32(x.x); x.y = to_tf32(x.y);
            x.z = to_tf32(x.z); x.w = to_tf32(x.w);
            *(float4*)(&Bs[row][col]) = x;
        }
        __syncthreads();

        #pragma unroll
        for (int kk = 0; kk < BK; kk += 8) {
            uint32_t af[MT][4];
            uint32_t bf[NT][2];
            #pragma unroll
            for (int mi = 0; mi < MT; ++mi) {
                int r = wm * WM + mi * 16;
                af[mi][0] = __float_as_uint(As[r + g    ][kk + t4    ]);
                af[mi][1] = __float_as_uint(As[r + g + 8][kk + t4    ]);
                af[mi][2] = __float_as_uint(As[r + g    ][kk + t4 + 4]);
                af[mi][3] = __float_as_uint(As[r + g + 8][kk + t4 + 4]);
            }
            #pragma unroll
            for (int ni = 0; ni < NT; ++ni) {
                int c = wn * WN + ni * 8 + g;
                bf[ni][0] = __float_as_uint(Bs[kk + t4    ][c]);
                bf[ni][1] = __float_as_uint(Bs[kk + t4 + 4][c]);
            }
            #pragma unroll
            for (int mi = 0; mi < MT; ++mi)
                #pragma unroll
                for (int ni = 0; ni < NT; ++ni)
                    mma_tf32(acc[mi][ni], af[mi][0], af[mi][1], af[mi][2], af[mi][3],
                             bf[ni][0], bf[ni][1]);
        }
        __syncthreads();
    }

    #pragma unroll
    for (int mi = 0; mi < MT; ++mi) {
        #pragma unroll
        for (int ni = 0; ni < NT; ++ni) {
            #pragma unroll
            for (int e = 0; e < 4; ++e) {
                int row = bm + wm * WM + mi * 16 + g + ((e >= 2) ? 8 : 0);
                int col = bn + wn * WN + ni * 8 + t4 * 2 + (e & 1);
                float v = acc[mi][ni][e] + bias[col];
                if (EPI == 0) {
                    out[(size_t)row * DMODEL + col] = v;
                } else {
                    int b  = row >> 11;
                    int l  = row & (SEQ - 1);
                    int h  = col >> 6;
                    int dh = col & (HDIM - 1);
                    out[(((size_t)(b * HEADS + h)) * SEQ + l) * HDIM + dh] = v;
                }
            }
        }
    }
}

// ============================================================================
// Fused attention: S = QK^T (tf32 mma) -> online softmax stats (pass 1)
//                  -> recompute S, write normalized P to gmem, PV mma (pass 2)
// One block = 128 query rows of one (b,h). 8 warps, warp = 16 rows x 128 cols.
// smem (dynamic, 147456 B):
//   Ks [128][68]  : K tile, [t][dh], tf32
//   Vs [128][72]  : V tile, [t][dv], tf32
//   Ps [128][132] : P staging fp32 (unioned with Qs [128][68])
//   Mf [2048]     : mask as additive 0 / -inf
// ============================================================================
#define KS_OFF   0
#define VS_OFF   8704
#define PS_OFF   17920
#define MASK_OFF 34816
#define SMEM_FLOATS 36864
#define SMEM_BYTES  (SMEM_FLOATS*4)

__global__ void __launch_bounds__(256, 1)
fused_attn(const float* __restrict__ gQ, const float* __restrict__ gK,
           const float* __restrict__ gV, const int* __restrict__ mask,
           float* __restrict__ attnOut, float* __restrict__ gO)
{
    extern __shared__ float sm[];
    float* Ks = sm + KS_OFF;
    float* Vs = sm + VS_OFF;
    float* Ps = sm + PS_OFF;
    float* Qs = sm + PS_OFF;      // union: Qs dead before Ps live
    float* Mf = sm + MASK_OFF;

    const int tid  = threadIdx.x;
    const int lane = tid & 31;
    const int warp = tid >> 5;
    const int g    = lane >> 2;
    const int t4   = lane & 3;
    const int wrow = warp * 16;

    const int qb = blockIdx.x * QB;
    const int bh = blockIdx.y;
    const int zb = bh >> 4;           // bh / HEADS
    const int zh = bh & 15;           // bh % HEADS

    const float* Q = gQ + ((size_t)bh * SEQ + qb) * HDIM;
    const float* K = gK + (size_t)bh * SEQ * HDIM;
    const float* V = gV + (size_t)bh * SEQ * HDIM;
    float* attn = attnOut + ((size_t)(zh * BATCH + zb) * SEQ + qb) * SEQ;

    // mask -> additive float
    #pragma unroll
    for (int i = 0; i < SEQ / 256; ++i) {
        int c = i * 256 + tid;
        Mf[c] = mask[zb * SEQ + c] ? NEG_INF : 0.f;
    }
    // Q tile -> smem (tf32)
    #pragma unroll
    for (int i = 0; i < 8; ++i) {
        int idx = i * 256 + tid;
        int r = idx >> 4, c4 = (idx & 15) << 2;
        float4 x = *(const float4*)(Q + (size_t)r * HDIM + c4);
        x.x = to_tf32(x.x); x.y = to_tf32(x.y);
        x.z = to_tf32(x.z); x.w = to_tf32(x.w);
        *(float4*)(Qs + r * 68 + c4) = x;
    }
    __syncthreads();

    // persistent Q A-fragments (K=64 -> 8 k-steps)
    uint32_t aq[8][4];
    #pragma unroll
    for (int kk8 = 0; kk8 < 8; ++kk8) {
        int kk = kk8 * 8;
        aq[kk8][0] = __float_as_uint(Qs[(wrow + g    ) * 68 + kk + t4    ]);
        aq[kk8][1] = __float_as_uint(Qs[(wrow + g + 8) * 68 + kk + t4    ]);
        aq[kk8][2] = __float_as_uint(Qs[(wrow + g    ) * 68 + kk + t4 + 4]);
        aq[kk8][3] = __float_as_uint(Qs[(wrow + g + 8) * 68 + kk + t4 + 4]);
    }

    // ---------------- pass 1: online (m, l) ----------------
    float m0 = NEG_INF, m1 = NEG_INF, l0 = 0.f, l1 = 0.f;

    for (int t = 0; t < SEQ / TC; ++t) {
        __syncthreads();
        const float* Kt = K + (size_t)t * TC * HDIM;
        #pragma unroll
        for (int i = 0; i < 8; ++i) {
            int idx = i * 256 + tid;
            int r = idx >> 4, c4 = (idx & 15) << 2;
            float4 x = *(const float4*)(Kt + (size_t)r * HDIM + c4);
            x.x = to_tf32(x.x); x.y = to_tf32(x.y);
            x.z = to_tf32(x.z); x.w = to_tf32(x.w);
            *(float4*)(Ks + r * 68 + c4) = x;
        }
        __syncthreads();

        float sacc[16][4];
        #pragma unroll
        for (int nt = 0; nt < 16; ++nt)
            #pragma unroll
            for (int e = 0; e < 4; ++e) sacc[nt][e] = 0.f;

        #pragma unroll
        for (int kk8 = 0; kk8 < 8; ++kk8) {
            int kk = kk8 * 8;
            #pragma unroll
            for (int nt = 0; nt < 16; ++nt) {
                uint32_t b0 = __float_as_uint(Ks[(nt * 8 + g) * 68 + kk + t4    ]);
                uint32_t b1 = __float_as_uint(Ks[(nt * 8 + g) * 68 + kk + t4 + 4]);
                mma_tf32(sacc[nt], aq[kk8][0], aq[kk8][1], aq[kk8][2], aq[kk8][3], b0, b1);
            }
        }

        float tm0 = NEG_INF, tm1 = NEG_INF;
        #pragma unroll
        for (int nt = 0; nt < 16; ++nt) {
            float mk0 = Mf[t * TC + nt * 8 + t4 * 2];
            float mk1 = Mf[t * TC + nt * 8 + t4 * 2 + 1];
            sacc[nt][0] = sacc[nt][0] * SCALE2 + mk0;
            sacc[nt][1] = sacc[nt][1] * SCALE2 + mk1;
            sacc[nt][2] = sacc[nt][2] * SCALE2 + mk0;
            sacc[nt][3] = sacc[nt][3] * SCALE2 + mk1;
            tm0 = fmaxf(tm0, fmaxf(sacc[nt][0], sacc[nt][1]));
            tm1 = fmaxf(tm1, fmaxf(sacc[nt][2], sacc[nt][3]));
        }
        tm0 = fmaxf(tm0, __shfl_xor_sync(0xffffffffu, tm0, 1));
        tm0 = fmaxf(tm0, __shfl_xor_sync(0xffffffffu, tm0, 2));
        tm1 = fmaxf(tm1, __shfl_xor_sync(0xffffffffu, tm1, 1));
        tm1 = fmaxf(tm1, __shfl_xor_sync(0xffffffffu, tm1, 2));

        float mn0 = fmaxf(m0, tm0), mn1 = fmaxf(m1, tm1);
        float ms0 = (mn0 == NEG_INF) ? 0.f : mn0;
        float ms1 = (mn1 == NEG_INF) ? 0.f : mn1;

        float sum0 = 0.f, sum1 = 0.f;
        #pragma unroll
        for (int nt = 0; nt < 16; ++nt) {
            sum0 += ex2(sacc[nt][0] - ms0) + ex2(sacc[nt][1] - ms0);
            sum1 += ex2(sacc[nt][2] - ms1) + ex2(sacc[nt][3] - ms1);
        }
        sum0 += __shfl_xor_sync(0xffffffffu, sum0, 1);
        sum0 += __shfl_xor_sync(0xffffffffu, sum0, 2);
        sum1 += __shfl_xor_sync(0xffffffffu, sum1, 1);
        sum1 += __shfl_xor_sync(0xffffffffu, sum1, 2);

        float a0 = (m0 == NEG_INF) ? 0.f : ex2(m0 - ms0);
        float a1 = (m1 == NEG_INF) ? 0.f : ex2(m1 - ms1);
        l0 = l0 * a0 + sum0;
        l1 = l1 * a1 + sum1;
        m0 = mn0; m1 = mn1;
    }

    const float invl0 = (l0 > 0.f) ? 1.f / l0 : 0.f;
    const float invl1 = (l1 > 0.f) ? 1.f / l1 : 0.f;
    const float mf0 = (m0 == NEG_INF) ? 0.f : m0;
    const float mf1 = (m1 == NEG_INF) ? 0.f : m1;

    // ---------------- pass 2: P write + PV ----------------
    float oacc[8][4];
    #pragma unroll
    for (int nt = 0; nt < 8; ++nt)
        #pragma unroll
        for (int e = 0; e < 4; ++e) oacc[nt][e] = 0.f;

    for (int t = 0; t < SEQ / TC; ++t) {
        __syncthreads();
        const float* Kt = K + (size_t)t * TC * HDIM;
        const float* Vt = V + (size_t)t * TC * HDIM;
        #pragma unroll
        for (int i = 0; i < 8; ++i) {
            int idx = i * 256 + tid;
            int r = idx >> 4, c4 = (idx & 15) << 2;
            float4 x = *(const float4*)(Kt + (size_t)r * HDIM + c4);
            x.x = to_tf32(x.x); x.y = to_tf32(x.y);
            x.z = to_tf32(x.z); x.w = to_tf32(x.w);
            *(float4*)(Ks + r * 68 + c4) = x;
            float4 y = *(const float4*)(Vt + (size_t)r * HDIM + c4);
            y.x = to_tf32(y.x); y.y = to_tf32(y.y);
            y.z = to_tf32(y.z); y.w = to_tf32(y.w);
            *(float4*)(Vs + r * 72 + c4) = y;
        }
        __syncthreads();

        float sacc[16][4];
        #pragma unroll
        for (int nt = 0; nt < 16; ++nt)
            #pragma unroll
            for (int e = 0; e < 4; ++e) sacc[nt][e] = 0.f;

        #pragma unroll
        for (int kk8 = 0; kk8 < 8; ++kk8) {
            int kk = kk8 * 8;
            #pragma unroll
            for (int nt = 0; nt < 16; ++nt) {
                uint32_t b0 = __float_as_uint(Ks[(nt * 8 + g) * 68 + kk + t4    ]);
                uint32_t b1 = __float_as_uint(Ks[(nt * 8 + g) * 68 + kk + t4 + 4]);
                mma_tf32(sacc[nt], aq[kk8][0], aq[kk8][1], aq[kk8][2], aq[kk8][3], b0, b1);
            }
        }

        // normalize + stage P
        #pragma unroll
        for (int nt = 0; nt < 16; ++nt) {
            float mk0 = Mf[t * TC + nt * 8 + t4 * 2];
            float mk1 = Mf[t * TC + nt * 8 + t4 * 2 + 1];
            float p00 = ex2(sacc[nt][0] * SCALE2 + mk0 - mf0) * invl0;
            float p01 = ex2(sacc[nt][1] * SCALE2 + mk1 - mf0) * invl0;
            float p10 = ex2(sacc[nt][2] * SCALE2 + mk0 - mf1) * invl1;
            float p11 = ex2(sacc[nt][3] * SCALE2 + mk1 - mf1) * invl1;
            Ps[(wrow + g    ) * 132 + nt * 8 + t4 * 2    ] = p00;
            Ps[(wrow + g    ) * 132 + nt * 8 + t4 * 2 + 1] = p01;
            Ps[(wrow + g + 8) * 132 + nt * 8 + t4 * 2    ] = p10;
            Ps[(wrow + g + 8) * 132 + nt * 8 + t4 * 2 + 1] = p11;
        }
        __syncthreads();

        // coalesced attn write (fp32, full precision)
        #pragma unroll
        for (int i = 0; i < 16; ++i) {
            int idx = i * 256 + tid;
            int r = idx >> 5, c4 = (idx & 31) << 2;
            float4 x = *(const float4*)(Ps + r * 132 + c4);
            *(float4*)(attn + (size_t)r * SEQ + t * TC + c4) = x;
        }

        // PV: O += P(16x128) @ V(128x64) per warp
        #pragma unroll
        for (int kt = 0; kt < 16; ++kt) {
            int kb = kt * 8;
            uint32_t a0 = __float_as_uint(to_tf32(Ps[(wrow + g    ) * 132 + kb + t4    ]));
            uint32_t a1 = __float_as_uint(to_tf32(Ps[(wrow + g + 8) * 132 + kb + t4    ]));
            uint32_t a2 = __float_as_uint(to_tf32(Ps[(wrow + g    ) * 132 + kb + t4 + 4]));
            uint32_t a3 = __float_as_uint(to_tf32(Ps[(wrow + g + 8) * 132 + kb + t4 + 4]));
            #pragma unroll
            for (int nt = 0; nt < 8; ++nt) {
                uint32_t b0 = __float_as_uint(Vs[(kb + t4    ) * 72 + nt * 8 + g]);
                uint32_t b1 = __float_as_uint(Vs[(kb + t4 + 4) * 72 + nt * 8 + g]);
                mma_tf32(oacc[nt], a0, a1, a2, a3, b0, b1);
            }
        }
    }

    // write O block to g_O [b*l][h*64+dv]
    #pragma unroll
    for (int nt = 0; nt < 8; ++nt) {
        #pragma unroll
        for (int e = 0; e < 4; ++e) {
            int rl  = wrow + g + ((e >= 2) ? 8 : 0);
            int col = nt * 8 + t4 * 2 + (e & 1);
            gO[((size_t)zb * SEQ + qb + rl) * DMODEL + zh * HDIM + col] = oacc[nt][e];
        }
    }
}

// ============================================================================
extern "C" void kernel_launch(void* const* d_in, const int* in_sizes, int n_in,
                              void* d_out, int out_size)
{
    const float* q    = (const float*)d_in[0];
    const float* k    = (const float*)d_in[1];
    const float* v    = (const float*)d_in[2];
    const int*   mask = (const int*)d_in[3];
    const float* Wq = (const float*)d_in[4];
    const float* bq = (const float*)d_in[5];
    const float* Wk = (const float*)d_in[6];
    const float* bk = (const float*)d_in[7];
    const float* Wv = (const float*)d_in[8];
    const float* bv = (const float*)d_in[9];
    const float* Wo = (const float*)d_in[10];
    const float* bo = (const float*)d_in[11];

    float* out  = (float*)d_out;                         // [4,2048,1024]
    float* attn = out + (size_t)TOK * DMODEL;            // [16,4,2048,2048]

    float *gq, *gk, *gv, *go;
    cudaGetSymbolAddress((void**)&gq, g_Q);
    cudaGetSymbolAddress((void**)&gk, g_K);
    cudaGetSymbolAddress((void**)&gv, g_V);
    cudaGetSymbolAddress((void**)&go, g_O);

    static int smem_set = 0;
    if (!smem_set) {
        cudaFuncSetAttribute(fused_attn, cudaFuncAttributeMaxDynamicSharedMemorySize, SMEM_BYTES);
        smem_set = 1;
    }

    dim3 blk(256);

    // Q/K/V projections
    dim3 gproj(DMODEL / 128, TOK / 128, 1);
    gemm_mma<128,128,32,32,64,1><<<gproj, blk>>>(q, Wq, bq, gq, DMODEL, DMODEL, DMODEL);
    gemm_mma<128,128,32,32,64,1><<<gproj, blk>>>(k, Wk, bk, gk, DMODEL, DMODEL, DMODEL);
    gemm_mma<128,128,32,32,64,1><<<gproj, blk>>>(v, Wv, bv, gv, DMODEL, DMODEL, DMODEL);

    // fused scores + softmax + attn-write + PV
    dim3 gfa(SEQ / QB, BATCH * HEADS);
    fused_attn<<<gfa, blk, SMEM_BYTES>>>(gq, gk, gv, mask, attn, go);

    // output projection
    gemm_mma<128,128,32,32,64,0><<<gproj, blk>>>(go, Wo, bo, out, DMODEL, DMODEL, DMODEL);
}

// round 5
// speedup vs baseline: 1.3735x; 1.0896x over previous
#include <cuda_runtime.h>
#include <cstdint>

#define BATCH   4
#define HEADS   16
#define SEQ     2048
#define DMODEL  1024
#define HDIM    64
#define TOK     (BATCH*SEQ)       // 8192
// softmax in exp2 domain: scale = (1/sqrt(64)) * log2(e)
#define SCALE2  0.18033688011112042f

#define QB      128               // query rows per fused block
#define TC      64                // key tile (shrunk for 2 CTAs/SM)

// -------- scratch (allocation-free rule: __device__ globals) --------
__device__ float g_Q[BATCH*HEADS*SEQ*HDIM];   // [b][h][l][dh]
__device__ float g_K[BATCH*HEADS*SEQ*HDIM];
__device__ float g_V[BATCH*HEADS*SEQ*HDIM];
__device__ float g_O[TOK*DMODEL];             // [b*l][h*64+dh]

__device__ __forceinline__ float to_tf32(float x) {
    float r;
    asm("cvt.rna.tf32.f32 %0, %1;" : "=f"(r) : "f"(x));
    return r;
}

__device__ __forceinline__ float ex2(float x) {
    float r;
    asm("ex2.approx.f32 %0, %1;" : "=f"(r) : "f"(x));
    return r;
}

__device__ __forceinline__ void mma_tf32(float c[4],
    uint32_t a0, uint32_t a1, uint32_t a2, uint32_t a3,
    uint32_t b0, uint32_t b1)
{
    asm volatile(
        "mma.sync.aligned.m16n8k8.row.col.f32.tf32.tf32.f32 "
        "{%0,%1,%2,%3}, {%4,%5,%6,%7}, {%8,%9}, {%0,%1,%2,%3};\n"
        : "+f"(c[0]), "+f"(c[1]), "+f"(c[2]), "+f"(c[3])
        : "r"(a0), "r"(a1), "r"(a2), "r"(a3), "r"(b0), "r"(b1));
}

#define NEG_INF __int_as_float(0xff800000)

// ============================================================================
// Projection / output GEMM (TF32 mma). EPI 0: +bias, row-major out.
// EPI 1: +bias, scatter to [b][h][l][dh].   2 CTAs/SM target.
// ============================================================================
template<int BM, int BN, int BK, int WM, int WN, int EPI>
__global__ void __launch_bounds__(256, 2)
gemm_mma(const float* __restrict__ Ag, const float* __restrict__ Bg,
         const float* __restrict__ bias, float* __restrict__ out,
         int K, int lda, int ldb)
{
    constexpr int WARPS_M = BM / WM;
    constexpr int MT = WM / 16;
    constexpr int NT = WN / 8;
    constexpr int PAD = 4;

    __shared__ float As[BM][BK + PAD];
    __shared__ float Bs[BK][BN + PAD];

    const int tid  = threadIdx.x;
    const int warp = tid >> 5;
    const int lane = tid & 31;
    const int wm   = warp % WARPS_M;
    const int wn   = warp / WARPS_M;
    const int g    = lane >> 2;
    const int t4   = lane & 3;

    const int bn = blockIdx.x * BN;
    const int bm = blockIdx.y * BM;

    float acc[MT][NT][4];
    #pragma unroll
    for (int mi = 0; mi < MT; ++mi)
        #pragma unroll
        for (int ni = 0; ni < NT; ++ni)
            #pragma unroll
            for (int e = 0; e < 4; ++e) acc[mi][ni][e] = 0.f;

    for (int k0 = 0; k0 < K; k0 += BK) {
        constexpr int AV = BM * BK / 4;
        #pragma unroll
        for (int i = 0; i < AV / 256; ++i) {
            int v = i * 256 + tid;
            int row = v / (BK / 4);
            int kc  = (v % (BK / 4)) * 4;
            float4 x = *(const float4*)(Ag + (size_t)(bm + row) * lda + k0 + kc);
            x.x = to_tf32(x.x); x.y = to_tf32(x.y);
            x.z = to_tf32(x.z); x.w = to_tf32(x.w);
            *(float4*)(&As[row][kc]) = x;
        }
        constexpr int BV = BK * BN / 4;
        #pragma unroll
        for (int i = 0; i < BV / 256; ++i) {
            int v = i * 256 + tid;
            int row = v / (BN / 4);
            int col = (v % (BN / 4)) * 4;
            float4 x = *(const float4*)(Bg + (size_t)(k0 + row) * ldb + bn + col);
            x.x = to_tf32(x.x); x.y = to_tf32(x.y);
            x.z = to_tf32(x.z); x.w = to_tf32(x.w);
            *(float4*)(&Bs[row][col]) = x;
        }
        __syncthreads();

        #pragma unroll
        for (int kk = 0; kk < BK; kk += 8) {
            uint32_t af[MT][4];
            uint32_t bf[NT][2];
            #pragma unroll
            for (int mi = 0; mi < MT; ++mi) {
                int r = wm * WM + mi * 16;
                af[mi][0] = __float_as_uint(As[r + g    ][kk + t4    ]);
                af[mi][1] = __float_as_uint(As[r + g + 8][kk + t4    ]);
                af[mi][2] = __float_as_uint(As[r + g    ][kk + t4 + 4]);
                af[mi][3] = __float_as_uint(As[r + g + 8][kk + t4 + 4]);
            }
            #pragma unroll
            for (int ni = 0; ni < NT; ++ni) {
                int c = wn * WN + ni * 8 + g;
                bf[ni][0] = __float_as_uint(Bs[kk + t4    ][c]);
                bf[ni][1] = __float_as_uint(Bs[kk + t4 + 4][c]);
            }
            #pragma unroll
            for (int mi = 0; mi < MT; ++mi)
                #pragma unroll
                for (int ni = 0; ni < NT; ++ni)
                    mma_tf32(acc[mi][ni], af[mi][0], af[mi][1], af[mi][2], af[mi][3],
                             bf[ni][0], bf[ni][1]);
        }
        __syncthreads();
    }

    #pragma unroll
    for (int mi = 0; mi < MT; ++mi) {
        #pragma unroll
        for (int ni = 0; ni < NT; ++ni) {
            #pragma unroll
            for (int e = 0; e < 4; ++e) {
                int row = bm + wm * WM + mi * 16 + g + ((e >= 2) ? 8 : 0);
                int col = bn + wn * WN + ni * 8 + t4 * 2 + (e & 1);
                float v = acc[mi][ni][e] + bias[col];
                if (EPI == 0) {
                    out[(size_t)row * DMODEL + col] = v;
                } else {
                    int b  = row >> 11;
                    int l  = row & (SEQ - 1);
                    int h  = col >> 6;
                    int dh = col & (HDIM - 1);
                    out[(((size_t)(b * HEADS + h)) * SEQ + l) * HDIM + dh] = v;
                }
            }
        }
    }
}

// ============================================================================
// Fused attention v2: TC=64 key tiles, no P smem staging (shuffle C->A frags),
// direct attn register writes. Targets 2 CTAs/SM (<=128 regs, 43KB smem).
// smem floats: Ks[64][68] @0 (4352) | Vs[64][72] @4352 (4608) | Mf @8960 (2048)
// Qs[128][68] (8704) overlays Ks+Vs during init only.
// ============================================================================
#define KS_OFF   0
#define VS_OFF   4352
#define MASK_OFF 8960
#define SMEM_FLOATS 11008
#define SMEM_BYTES  (SMEM_FLOATS*4)

__global__ void __launch_bounds__(256, 2)
fused_attn(const float* __restrict__ gQ, const float* __restrict__ gK,
           const float* __restrict__ gV, const int* __restrict__ mask,
           float* __restrict__ attnOut, float* __restrict__ gO)
{
    extern __shared__ float sm[];
    float* Ks = sm + KS_OFF;
    float* Vs = sm + VS_OFF;
    float* Qs = sm;               // overlay, dead after aq extraction
    float* Mf = sm + MASK_OFF;

    const int tid  = threadIdx.x;
    const int lane = tid & 31;
    const int warp = tid >> 5;
    const int g    = lane >> 2;
    const int t4   = lane & 3;
    const int wrow = warp * 16;

    const int qb = blockIdx.x * QB;
    const int bh = blockIdx.y;
    const int zb = bh >> 4;
    const int zh = bh & 15;

    const float* Q = gQ + ((size_t)bh * SEQ + qb) * HDIM;
    const float* K = gK + (size_t)bh * SEQ * HDIM;
    const float* V = gV + (size_t)bh * SEQ * HDIM;
    float* attn = attnOut + ((size_t)(zh * BATCH + zb) * SEQ + qb) * SEQ;

    // mask -> additive float
    #pragma unroll
    for (int i = 0; i < SEQ / 256; ++i) {
        int c = i * 256 + tid;
        Mf[c] = mask[zb * SEQ + c] ? NEG_INF : 0.f;
    }
    // Q tile -> smem (tf32), then extract persistent A-fragments
    #pragma unroll
    for (int i = 0; i < 8; ++i) {
        int idx = i * 256 + tid;
        int r = idx >> 4, c4 = (idx & 15) << 2;
        float4 x = *(const float4*)(Q + (size_t)r * HDIM + c4);
        x.x = to_tf32(x.x); x.y = to_tf32(x.y);
        x.z = to_tf32(x.z); x.w = to_tf32(x.w);
        *(float4*)(Qs + r * 68 + c4) = x;
    }
    __syncthreads();

    uint32_t aq[8][4];
    #pragma unroll
    for (int kk8 = 0; kk8 < 8; ++kk8) {
        int kk = kk8 * 8;
        aq[kk8][0] = __float_as_uint(Qs[(wrow + g    ) * 68 + kk + t4    ]);
        aq[kk8][1] = __float_as_uint(Qs[(wrow + g + 8) * 68 + kk + t4    ]);
        aq[kk8][2] = __float_as_uint(Qs[(wrow + g    ) * 68 + kk + t4 + 4]);
        aq[kk8][3] = __float_as_uint(Qs[(wrow + g + 8) * 68 + kk + t4 + 4]);
    }

    // ---------------- pass 1: online (m, l) ----------------
    float m0 = NEG_INF, m1 = NEG_INF, l0 = 0.f, l1 = 0.f;

    for (int t = 0; t < SEQ / TC; ++t) {
        __syncthreads();
        const float* Kt = K + (size_t)t * TC * HDIM;
        #pragma unroll
        for (int i = 0; i < 4; ++i) {
            int idx = i * 256 + tid;
            int r = idx >> 4, c4 = (idx & 15) << 2;
            float4 x = *(const float4*)(Kt + (size_t)r * HDIM + c4);
            x.x = to_tf32(x.x); x.y = to_tf32(x.y);
            x.z = to_tf32(x.z); x.w = to_tf32(x.w);
            *(float4*)(Ks + r * 68 + c4) = x;
        }
        __syncthreads();

        float sacc[8][4];
        #pragma unroll
        for (int nt = 0; nt < 8; ++nt)
            #pragma unroll
            for (int e = 0; e < 4; ++e) sacc[nt][e] = 0.f;

        #pragma unroll
        for (int kk8 = 0; kk8 < 8; ++kk8) {
            int kk = kk8 * 8;
            #pragma unroll
            for (int nt = 0; nt < 8; ++nt) {
                uint32_t b0 = __float_as_uint(Ks[(nt * 8 + g) * 68 + kk + t4    ]);
                uint32_t b1 = __float_as_uint(Ks[(nt * 8 + g) * 68 + kk + t4 + 4]);
                mma_tf32(sacc[nt], aq[kk8][0], aq[kk8][1], aq[kk8][2], aq[kk8][3], b0, b1);
            }
        }

        float tm0 = NEG_INF, tm1 = NEG_INF;
        #pragma unroll
        for (int nt = 0; nt < 8; ++nt) {
            float mk0 = Mf[t * TC + nt * 8 + t4 * 2];
            float mk1 = Mf[t * TC + nt * 8 + t4 * 2 + 1];
            sacc[nt][0] = sacc[nt][0] * SCALE2 + mk0;
            sacc[nt][1] = sacc[nt][1] * SCALE2 + mk1;
            sacc[nt][2] = sacc[nt][2] * SCALE2 + mk0;
            sacc[nt][3] = sacc[nt][3] * SCALE2 + mk1;
            tm0 = fmaxf(tm0, fmaxf(sacc[nt][0], sacc[nt][1]));
            tm1 = fmaxf(tm1, fmaxf(sacc[nt][2], sacc[nt][3]));
        }
        tm0 = fmaxf(tm0, __shfl_xor_sync(0xffffffffu, tm0, 1));
        tm0 = fmaxf(tm0, __shfl_xor_sync(0xffffffffu, tm0, 2));
        tm1 = fmaxf(tm1, __shfl_xor_sync(0xffffffffu, tm1, 1));
        tm1 = fmaxf(tm1, __shfl_xor_sync(0xffffffffu, tm1, 2));

        float mn0 = fmaxf(m0, tm0), mn1 = fmaxf(m1, tm1);
        float ms0 = (mn0 == NEG_INF) ? 0.f : mn0;
        float ms1 = (mn1 == NEG_INF) ? 0.f : mn1;

        float sum0 = 0.f, sum1 = 0.f;
        #pragma unroll
        for (int nt = 0; nt < 8; ++nt) {
            sum0 += ex2(sacc[nt][0] - ms0) + ex2(sacc[nt][1] - ms0);
            sum1 += ex2(sacc[nt][2] - ms1) + ex2(sacc[nt][3] - ms1);
        }
        sum0 += __shfl_xor_sync(0xffffffffu, sum0, 1);
        sum0 += __shfl_xor_sync(0xffffffffu, sum0, 2);
        sum1 += __shfl_xor_sync(0xffffffffu, sum1, 1);
        sum1 += __shfl_xor_sync(0xffffffffu, sum1, 2);

        float a0 = (m0 == NEG_INF) ? 0.f : ex2(m0 - ms0);
        float a1 = (m1 == NEG_INF) ? 0.f : ex2(m1 - ms1);
        l0 = l0 * a0 + sum0;
        l1 = l1 * a1 + sum1;
        m0 = mn0; m1 = mn1;
    }

    const float invl0 = (l0 > 0.f) ? 1.f / l0 : 0.f;
    const float invl1 = (l1 > 0.f) ? 1.f / l1 : 0.f;
    const float mf0 = (m0 == NEG_INF) ? 0.f : m0;
    const float mf1 = (m1 == NEG_INF) ? 0.f : m1;

    // ---------------- pass 2: P write + PV (no smem staging) ----------------
    float oacc[8][4];
    #pragma unroll
    for (int nt = 0; nt < 8; ++nt)
        #pragma unroll
        for (int e = 0; e < 4; ++e) oacc[nt][e] = 0.f;

    const int srcA = (lane & ~3) | (t4 >> 1);   // col t4  source lane
    const int srcB = srcA + 2;                  // col t4+4 source lane
    const bool odd = (t4 & 1);

    for (int t = 0; t < SEQ / TC; ++t) {
        __syncthreads();
        const float* Kt = K + (size_t)t * TC * HDIM;
        const float* Vt = V + (size_t)t * TC * HDIM;
        #pragma unroll
        for (int i = 0; i < 4; ++i) {
            int idx = i * 256 + tid;
            int r = idx >> 4, c4 = (idx & 15) << 2;
            float4 x = *(const float4*)(Kt + (size_t)r * HDIM + c4);
            x.x = to_tf32(x.x); x.y = to_tf32(x.y);
            x.z = to_tf32(x.z); x.w = to_tf32(x.w);
            *(float4*)(Ks + r * 68 + c4) = x;
            float4 y = *(const float4*)(Vt + (size_t)r * HDIM + c4);
            y.x = to_tf32(y.x); y.y = to_tf32(y.y);
            y.z = to_tf32(y.z); y.w = to_tf32(y.w);
            *(float4*)(Vs + r * 72 + c4) = y;
        }
        __syncthreads();

        float sacc[8][4];
        #pragma unroll
        for (int nt = 0; nt < 8; ++nt)
            #pragma unroll
            for (int e = 0; e < 4; ++e) sacc[nt][e] = 0.f;

        #pragma unroll
        for (int kk8 = 0; kk8 < 8; ++kk8) {
            int kk = kk8 * 8;
            #pragma unroll
            for (int nt = 0; nt < 8; ++nt) {
                uint32_t b0 = __float_as_uint(Ks[(nt * 8 + g) * 68 + kk + t4    ]);
                uint32_t b1 = __float_as_uint(Ks[(nt * 8 + g) * 68 + kk + t4 + 4]);
                mma_tf32(sacc[nt], aq[kk8][0], aq[kk8][1], aq[kk8][2], aq[kk8][3], b0, b1);
            }
        }

        // normalize in place + direct attn write (float2, sector-aligned)
        #pragma unroll
        for (int nt = 0; nt < 8; ++nt) {
            float mk0 = Mf[t * TC + nt * 8 + t4 * 2];
            float mk1 = Mf[t * TC + nt * 8 + t4 * 2 + 1];
            sacc[nt][0] = ex2(sacc[nt][0] * SCALE2 + mk0 - mf0) * invl0;
            sacc[nt][1] = ex2(sacc[nt][1] * SCALE2 + mk1 - mf0) * invl0;
            sacc[nt][2] = ex2(sacc[nt][2] * SCALE2 + mk0 - mf1) * invl1;
            sacc[nt][3] = ex2(sacc[nt][3] * SCALE2 + mk1 - mf1) * invl1;
            float* d0 = attn + (size_t)(wrow + g) * SEQ + t * TC + nt * 8 + t4 * 2;
            *(float2*)d0 = make_float2(sacc[nt][0], sacc[nt][1]);
            *(float2*)(d0 + 8 * SEQ) = make_float2(sacc[nt][2], sacc[nt][3]);
        }

        // PV: A-fragments from sacc via lane shuffles (C->A layout permute)
        #pragma unroll
        for (int kt = 0; kt < 8; ++kt) {
            float x0 = __shfl_sync(0xffffffffu, sacc[kt][0], srcA);
            float x1 = __shfl_sync(0xffffffffu, sacc[kt][1], srcA);
            float y0 = __shfl_sync(0xffffffffu, sacc[kt][0], srcB);
            float y1 = __shfl_sync(0xffffffffu, sacc[kt][1], srcB);
            float z0 = __shfl_sync(0xffffffffu, sacc[kt][2], srcA);
            float z1 = __shfl_sync(0xffffffffu, sacc[kt][3], srcA);
            float w0 = __shfl_sync(0xffffffffu, sacc[kt][2], srcB);
            float w1 = __shfl_sync(0xffffffffu, sacc[kt][3], srcB);
            uint32_t a0 = __float_as_uint(to_tf32(odd ? x1 : x0));
            uint32_t a1 = __float_as_uint(to_tf32(odd ? z1 : z0));
            uint32_t a2 = __float_as_uint(to_tf32(odd ? y1 : y0));
            uint32_t a3 = __float_as_uint(to_tf32(odd ? w1 : w0));
            int kb = kt * 8;
            #pragma unroll
            for (int nt = 0; nt < 8; ++nt) {
                uint32_t b0 = __float_as_uint(Vs[(kb + t4    ) * 72 + nt * 8 + g]);
                uint32_t b1 = __float_as_uint(Vs[(kb + t4 + 4) * 72 + nt * 8 + g]);
                mma_tf32(oacc[nt], a0, a1, a2, a3, b0, b1);
            }
        }
    }

    // write O block to g_O [b*l][h*64+dv]
    #pragma unroll
    for (int nt = 0; nt < 8; ++nt) {
        #pragma unroll
        for (int e = 0; e < 4; ++e) {
            int rl  = wrow + g + ((e >= 2) ? 8 : 0);
            int col = nt * 8 + t4 * 2 + (e & 1);
            gO[((size_t)zb * SEQ + qb + rl) * DMODEL + zh * HDIM + col] = oacc[nt][e];
        }
    }
}

// ============================================================================
extern "C" void kernel_launch(void* const* d_in, const int* in_sizes, int n_in,
                              void* d_out, int out_size)
{
    const float* q    = (const float*)d_in[0];
    const float* k    = (const float*)d_in[1];
    const float* v    = (const float*)d_in[2];
    const int*   mask = (const int*)d_in[3];
    const float* Wq = (const float*)d_in[4];
    const float* bq = (const float*)d_in[5];
    const float* Wk = (const float*)d_in[6];
    const float* bk = (const float*)d_in[7];
    const float* Wv = (const float*)d_in[8];
    const float* bv = (const float*)d_in[9];
    const float* Wo = (const float*)d_in[10];
    const float* bo = (const float*)d_in[11];

    float* out  = (float*)d_out;                         // [4,2048,1024]
    float* attn = out + (size_t)TOK * DMODEL;            // [16,4,2048,2048]

    float *gq, *gk, *gv, *go;
    cudaGetSymbolAddress((void**)&gq, g_Q);
    cudaGetSymbolAddress((void**)&gk, g_K);
    cudaGetSymbolAddress((void**)&gv, g_V);
    cudaGetSymbolAddress((void**)&go, g_O);

    dim3 blk(256);
    dim3 gproj(DMODEL / 128, TOK / 128);

    // Q/K/V projections
    gemm_mma<128,128,32,32,64,1><<<gproj, blk>>>(q, Wq, bq, gq, DMODEL, DMODEL, DMODEL);
    gemm_mma<128,128,32,32,64,1><<<gproj, blk>>>(k, Wk, bk, gk, DMODEL, DMODEL, DMODEL);
    gemm_mma<128,128,32,32,64,1><<<gproj, blk>>>(v, Wv, bv, gv, DMODEL, DMODEL, DMODEL);

    // fused scores + softmax + attn-write + PV
    dim3 gfa(SEQ / QB, BATCH * HEADS);
    fused_attn<<<gfa, blk, SMEM_BYTES>>>(gq, gk, gv, mask, attn, go);

    // output projection
    gemm_mma<128,128,32,32,64,0><<<gproj, blk>>>(go, Wo, bo, out, DMODEL, DMODEL, DMODEL);
}